// round 10
// baseline (speedup 1.0000x reference)
#include <cuda_runtime.h>
#include <math.h>

#define BATCH 512
#define NNODE 513
#define NPAD  520          // padded node stride
#define DIM   256
#define NH    8
#define HDIM  32
#define TSTEPS 128
#define EWD   512          // U+1
#define NEGV  -1000000000.0f
#define INV_HD 0.176776695296636893f   // 1/sqrt(32)
#define INV_D  0.0625f                 // 1/sqrt(256)

// ---------------- static device scratch ----------------
// Transposed layouts: K,V = (b, h, d, n_pad)   L = (b, d, n_pad)
static __device__ float d_K[(size_t)BATCH * NH * HDIM * NPAD];
static __device__ float d_V[(size_t)BATCH * NH * HDIM * NPAD];
static __device__ float d_L[(size_t)BATCH * DIM * NPAD];
static __device__ float d_fixed[BATCH * DIM];
static __device__ float d_ctx[BATCH * DIM];      // ctx in ctx-space (exact reference recursion)
static __device__ unsigned char d_mask[BATCH * NNODE];

// 10*tanh(x) via expf so fast-math __tanhf can't perturb the argmax chain.
__device__ __forceinline__ float tanh10(float x) {
  float ax = fabsf(x);
  float t = expf(-2.0f * ax);
  float r = (1.0f - t) / (1.0f + t);
  return copysignf(10.0f * r, x);
}

// ---------------- precompute: graph mean -> fixed_ctx; init state ----------------
__global__ void k_precompute_fixed(const float* __restrict__ ne,
                                   const float* __restrict__ w_fc,
                                   const float* __restrict__ b_fc) {
  int b = blockIdx.x, tid = threadIdx.x;
  __shared__ float mean[DIM];
  const float* base = ne + (size_t)b * NNODE * DIM;
  float acc = 0.f;
  for (int n = 0; n < NNODE; ++n) acc += base[(size_t)n * DIM + tid];
  mean[tid] = acc / (float)NNODE;
  __syncthreads();
  float o = b_fc[tid];
  for (int d = 0; d < DIM; ++d) o += mean[d] * w_fc[d * DIM + tid];
  d_fixed[b * DIM + tid] = o;
  d_ctx[b * DIM + tid] = 0.f;
  for (int i = tid; i < NNODE; i += 256) d_mask[(size_t)b * NNODE + i] = 0;
}

// ---------------- precompute: KVL = node_embeds @ w_kvl + b, scattered transposed ----------------
__global__ void k_kvl(const float* __restrict__ ne,
                      const float* __restrict__ w,
                      const float* __restrict__ bias) {
  __shared__ float As[16][72];
  __shared__ float Bs[16][64];
  int tid = threadIdx.x;
  int tx = tid & 15, ty = tid >> 4;
  int row0 = blockIdx.x * 64;
  int col0 = blockIdx.y * 64;
  int ar = tid >> 2, ac4 = tid & 3;
  int br = tid >> 4, bc4 = tid & 15;
  float acc[4][4];
#pragma unroll
  for (int i = 0; i < 4; i++)
#pragma unroll
    for (int j = 0; j < 4; j++) acc[i][j] = 0.f;

  for (int k0 = 0; k0 < DIM; k0 += 16) {
    float4 av = *(const float4*)&ne[(size_t)(row0 + ar) * DIM + k0 + ac4 * 4];
    As[ac4 * 4 + 0][ar] = av.x;
    As[ac4 * 4 + 1][ar] = av.y;
    As[ac4 * 4 + 2][ar] = av.z;
    As[ac4 * 4 + 3][ar] = av.w;
    *(float4*)&Bs[br][bc4 * 4] =
        *(const float4*)&w[(size_t)(k0 + br) * 768 + col0 + bc4 * 4];
    __syncthreads();
#pragma unroll
    for (int k = 0; k < 16; k++) {
      float4 a = *(const float4*)&As[k][ty * 4];
      float4 bv = *(const float4*)&Bs[k][tx * 4];
      float am[4] = {a.x, a.y, a.z, a.w};
      float bm[4] = {bv.x, bv.y, bv.z, bv.w};
#pragma unroll
      for (int i = 0; i < 4; i++)
#pragma unroll
        for (int j = 0; j < 4; j++) acc[i][j] += am[i] * bm[j];
    }
    __syncthreads();
  }
#pragma unroll
  for (int i = 0; i < 4; i++) {
    int m = row0 + ty * 4 + i;
    int bb = m / NNODE;
    int n = m - bb * NNODE;
#pragma unroll
    for (int j = 0; j < 4; j++) {
      int col = col0 + tx * 4 + j;
      float v = acc[i][j] + bias[col];
      if (col < 256) {
        int h = col >> 5, dd = col & 31;
        d_K[(((size_t)bb * NH + h) * HDIM + dd) * NPAD + n] = v;
      } else if (col < 512) {
        int c = col - 256;
        int h = c >> 5, dd = c & 31;
        d_V[(((size_t)bb * NH + h) * HDIM + dd) * NPAD + n] = v;
      } else {
        d_L[((size_t)bb * DIM + (col - 512)) * NPAD + n] = v;
      }
    }
  }
}

// ---------------- fully-fused per-step kernel: one block per batch element ----------------
// q-matvec -> attention (8 heads) -> glimpse -> logits -> log_softmax -> argmax
// -> output -> edge matvec -> ctx update -> mask update.
// Every dot product is a single sequential ascending-k accumulation, bit-identical
// to the last passing kernel's arithmetic.
__global__ __launch_bounds__(512) void k_step(float* __restrict__ out,
                                              const float* __restrict__ ne,
                                              const float* __restrict__ ew,
                                              const float* __restrict__ w_sc,
                                              const float* __restrict__ b_sc,
                                              const float* __restrict__ w_edge,
                                              const float* __restrict__ b_edge,
                                              const float* __restrict__ w_out,
                                              const float* __restrict__ b_out,
                                              int t) {
  int b = blockIdx.x;
  int tid = threadIdx.x, lane = tid & 31, w = tid >> 5;   // 16 warps
  __shared__ float s_in[768];        // [ctx | ew_t], later reused as [sel | curr]
  __shared__ float s_q[DIM];
  __shared__ float s_at[NH][NPAD];
  __shared__ float s_heads[DIM];
  __shared__ float s_g[DIM];
  __shared__ float s_l[NNODE];
  __shared__ unsigned char s_mask[NNODE];
  __shared__ float s_rm[16];
  __shared__ int s_ri[16];
  __shared__ float s_rs[16];

  // ---- load ctx + ew_t + mask ----
  if (tid < DIM) s_in[tid] = d_ctx[b * DIM + tid];
  s_in[256 + tid] = ew[((size_t)b * TSTEPS + t) * EWD + tid];
  for (int i = tid; i < NNODE; i += 512) s_mask[i] = d_mask[(size_t)b * NNODE + i];
  __syncthreads();

  // ---- q[col] = (sum_k s_in[k]*w_sc[k][col] + b_sc[col]) + fixed[col], k ascending ----
  if (tid < DIM) {
    float acc = 0.f;
#pragma unroll 8
    for (int k = 0; k < 768; ++k) acc = fmaf(s_in[k], w_sc[(size_t)k * DIM + tid], acc);
    s_q[tid] = (acc + b_sc[tid]) + d_fixed[b * DIM + tid];
  }
  __syncthreads();

  // ---- compat: thread owns node tid (tid 0 also node 512), d ascending ----
  const float* Kb = d_K + (size_t)b * NH * HDIM * NPAD;
  for (int h = 0; h < NH; ++h) {
    const float* Kh = Kb + (size_t)h * HDIM * NPAD;
    float a0 = 0.f, a2 = 0.f;
#pragma unroll 8
    for (int d = 0; d < HDIM; ++d) {
      float qv = s_q[h * HDIM + d];
      const float* row = Kh + (size_t)d * NPAD;
      a0 = fmaf(row[tid], qv, a0);
      if (tid == 0) a2 = fmaf(row[512], qv, a2);
    }
    s_at[h][tid] = s_mask[tid] ? NEGV : a0 * INV_HD;
    if (tid == 0) s_at[h][512] = s_mask[512] ? NEGV : a2 * INV_HD;
  }
  __syncthreads();

  // ---- softmax per head: warp w < 8 handles head w (lane-stride-32 pattern) ----
  if (w < NH) {
    float m = -3.402823466e38f;
    for (int i = lane; i < NNODE; i += 32) m = fmaxf(m, s_at[w][i]);
#pragma unroll
    for (int o = 16; o; o >>= 1) m = fmaxf(m, __shfl_xor_sync(0xffffffffu, m, o));
    float s = 0.f;
    for (int i = lane; i < NNODE; i += 32) {
      float e = expf(s_at[w][i] - m);
      s_at[w][i] = e;
      s += e;
    }
#pragma unroll
    for (int o = 16; o; o >>= 1) s += __shfl_xor_sync(0xffffffffu, s, o);
    float inv = 1.0f / s;
    for (int i = lane; i < NNODE; i += 32) s_at[w][i] *= inv;
  }
  __syncthreads();

  // ---- heads: warp w -> head w>>1, dims (w&1)*16..+16 (same lane-stride dot) ----
  {
    int h = w >> 1;
    int j0 = (w & 1) * 16;
    const float* Vh = d_V + ((size_t)b * NH + h) * HDIM * NPAD;
    for (int j = 0; j < 16; ++j) {
      const float* row = Vh + (size_t)(j0 + j) * NPAD;
      float acc = 0.f;
      for (int i = lane; i < NNODE; i += 32) acc += s_at[h][i] * row[i];
#pragma unroll
      for (int o = 16; o; o >>= 1) acc += __shfl_xor_sync(0xffffffffu, acc, o);
      if (lane == 0) s_heads[h * HDIM + j0 + j] = acc;
    }
  }
  __syncthreads();

  // ---- glimpse = heads @ w_out + b_out (bias-init accumulator, d ascending) ----
  if (tid < DIM) {
    float g = b_out[tid];
#pragma unroll 8
    for (int d = 0; d < DIM; ++d) g = fmaf(s_heads[d], w_out[(size_t)d * DIM + tid], g);
    s_g[tid] = g;
  }
  __syncthreads();

  // ---- logits = tanh10(glimpse . L_n / 16), masked, d ascending ----
  {
    const float* Lb = d_L + (size_t)b * DIM * NPAD;
    float a0 = 0.f, a2 = 0.f;
#pragma unroll 8
    for (int d = 0; d < DIM; ++d) {
      float g = s_g[d];
      const float* row = Lb + (size_t)d * NPAD;
      a0 = fmaf(row[tid], g, a0);
      if (tid == 0) a2 = fmaf(row[512], g, a2);
    }
    s_l[tid] = s_mask[tid] ? NEGV : tanh10(a0 * INV_D);
    if (tid == 0) s_l[512] = s_mask[512] ? NEGV : tanh10(a2 * INV_D);
  }
  __syncthreads();

  // ---- argmax (first occurrence on ties) ----
  float m = -3.402823466e38f;
  int mi = NNODE;
  for (int i = tid; i < NNODE; i += 512) {
    float v = s_l[i];
    if (v > m) { m = v; mi = i; }
  }
#pragma unroll
  for (int o = 16; o; o >>= 1) {
    float om = __shfl_xor_sync(0xffffffffu, m, o);
    int oi = __shfl_xor_sync(0xffffffffu, mi, o);
    if (om > m || (om == m && oi < mi)) { m = om; mi = oi; }
  }
  if (lane == 0) { s_rm[w] = m; s_ri[w] = mi; }
  __syncthreads();
  float mm = s_rm[0];
  int bi = s_ri[0];
#pragma unroll
  for (int i = 1; i < 16; i++) {
    if (s_rm[i] > mm || (s_rm[i] == mm && s_ri[i] < bi)) { mm = s_rm[i]; bi = s_ri[i]; }
  }

  // ---- logsumexp ----
  float s = 0.f;
  for (int i = tid; i < NNODE; i += 512) s += expf(s_l[i] - mm);
#pragma unroll
  for (int o = 16; o; o >>= 1) s += __shfl_xor_sync(0xffffffffu, s, o);
  if (lane == 0) s_rs[w] = s;
  __syncthreads();
  float ss = s_rs[0];
#pragma unroll
  for (int i = 1; i < 16; i++) ss += s_rs[i];
  float lse = mm + logf(ss);

  float* ob = out + ((size_t)b * TSTEPS + t) * NNODE;
  for (int i = tid; i < NNODE; i += 512) ob[i] = s_l[i] - lse;
  __syncthreads();   // s_in reuse below must not race the q-phase (long done) or loads above

  // ---- edge matvec + ctx update (exact reference recursion, k ascending, sel|curr) ----
  if (tid < DIM) {
    s_in[tid]       = ne[((size_t)b * NNODE + bi) * DIM + tid];           // sel_emb
    s_in[DIM + tid] = ne[((size_t)b * NNODE + (NNODE - 1)) * DIM + tid];  // curr_emb
  }
  __syncthreads();
  if (tid < DIM) {
    float acc = 0.f;
#pragma unroll 8
    for (int k = 0; k < 512; ++k) acc = fmaf(s_in[k], w_edge[(size_t)k * DIM + tid], acc);
    float v = acc + b_edge[tid];
    float old = d_ctx[b * DIM + tid];
    d_ctx[b * DIM + tid] = old + (v - old) / (float)(t + 1);
  }
  if (tid == 0 && bi > 0) d_mask[(size_t)b * NNODE + bi] = 1;
}

// ---------------- launch ----------------
extern "C" void kernel_launch(void* const* d_in, const int* in_sizes, int n_in,
                              void* d_out, int out_size) {
  const float* ne     = (const float*)d_in[0];   // (B, N, D)
  const float* ew     = (const float*)d_in[1];   // (B, T, U+1)
  const float* w_kvl  = (const float*)d_in[2];   // (D, 3D)
  const float* b_kvl  = (const float*)d_in[3];
  const float* w_fc   = (const float*)d_in[4];   // (D, D)
  const float* b_fc   = (const float*)d_in[5];
  const float* w_sc   = (const float*)d_in[6];   // (768, D)
  const float* b_sc   = (const float*)d_in[7];
  const float* w_out  = (const float*)d_in[8];   // (D, D)
  const float* b_out  = (const float*)d_in[9];
  const float* w_edge = (const float*)d_in[10];  // (2D, D)
  const float* b_edge = (const float*)d_in[11];
  float* out = (float*)d_out;

  k_precompute_fixed<<<BATCH, 256>>>(ne, w_fc, b_fc);
  k_kvl<<<dim3((BATCH * NNODE) / 64, 768 / 64), 256>>>(ne, w_kvl, b_kvl);

  for (int t = 0; t < TSTEPS; ++t) {
    k_step<<<BATCH, 512>>>(out, ne, ew, w_sc, b_sc, w_edge, b_edge, w_out, b_out, t);
  }
}

// round 14
// speedup vs baseline: 1.4105x; 1.4105x over previous
#include <cuda_runtime.h>
#include <math.h>

#define BATCH 512
#define NNODE 513
#define NPAD  520          // padded node stride
#define DIM   256
#define NH    8
#define HDIM  32
#define TSTEPS 128
#define EWD   512          // U+1
#define NEGV  -1000000000.0f
#define INV_HD 0.176776695296636893f   // 1/sqrt(32)
#define INV_D  0.0625f                 // 1/sqrt(256)

// ---------------- static device scratch ----------------
// Transposed layouts: K,V = (b, h, d, n_pad)   L = (b, d, n_pad)
static __device__ float d_K[(size_t)BATCH * NH * HDIM * NPAD];
static __device__ float d_V[(size_t)BATCH * NH * HDIM * NPAD];
static __device__ float d_L[(size_t)BATCH * DIM * NPAD];
static __device__ float d_fixed[BATCH * DIM];
static __device__ float d_ctx[BATCH * DIM];      // exact reference recursion space
static __device__ float d_q[BATCH * DIM];
static __device__ int d_sel[BATCH];
static __device__ unsigned char d_mask[BATCH * NNODE];

// 10*tanh(x) via expf so fast-math __tanhf can't perturb the argmax chain.
__device__ __forceinline__ float tanh10(float x) {
  float ax = fabsf(x);
  float t = expf(-2.0f * ax);
  float r = (1.0f - t) / (1.0f + t);
  return copysignf(10.0f * r, x);
}

// ---------------- precompute: graph mean -> fixed_ctx; init state ----------------
__global__ void k_precompute_fixed(const float* __restrict__ ne,
                                   const float* __restrict__ w_fc,
                                   const float* __restrict__ b_fc) {
  int b = blockIdx.x, tid = threadIdx.x;
  __shared__ float mean[DIM];
  const float* base = ne + (size_t)b * NNODE * DIM;
  float acc = 0.f;
  for (int n = 0; n < NNODE; ++n) acc += base[(size_t)n * DIM + tid];
  mean[tid] = acc / (float)NNODE;
  __syncthreads();
  float o = b_fc[tid];
  for (int d = 0; d < DIM; ++d) o += mean[d] * w_fc[d * DIM + tid];
  d_fixed[b * DIM + tid] = o;
  d_ctx[b * DIM + tid] = 0.f;
  for (int i = tid; i < NNODE; i += 256) d_mask[(size_t)b * NNODE + i] = 0;
}

// ---------------- precompute: KVL = node_embeds @ w_kvl + b, scattered transposed ----------------
__global__ void k_kvl(const float* __restrict__ ne,
                      const float* __restrict__ w,
                      const float* __restrict__ bias) {
  __shared__ float As[16][72];
  __shared__ float Bs[16][64];
  int tid = threadIdx.x;
  int tx = tid & 15, ty = tid >> 4;
  int row0 = blockIdx.x * 64;
  int col0 = blockIdx.y * 64;
  int ar = tid >> 2, ac4 = tid & 3;
  int br = tid >> 4, bc4 = tid & 15;
  float acc[4][4];
#pragma unroll
  for (int i = 0; i < 4; i++)
#pragma unroll
    for (int j = 0; j < 4; j++) acc[i][j] = 0.f;

  for (int k0 = 0; k0 < DIM; k0 += 16) {
    float4 av = *(const float4*)&ne[(size_t)(row0 + ar) * DIM + k0 + ac4 * 4];
    As[ac4 * 4 + 0][ar] = av.x;
    As[ac4 * 4 + 1][ar] = av.y;
    As[ac4 * 4 + 2][ar] = av.z;
    As[ac4 * 4 + 3][ar] = av.w;
    *(float4*)&Bs[br][bc4 * 4] =
        *(const float4*)&w[(size_t)(k0 + br) * 768 + col0 + bc4 * 4];
    __syncthreads();
#pragma unroll
    for (int k = 0; k < 16; k++) {
      float4 a = *(const float4*)&As[k][ty * 4];
      float4 bv = *(const float4*)&Bs[k][tx * 4];
      float am[4] = {a.x, a.y, a.z, a.w};
      float bm[4] = {bv.x, bv.y, bv.z, bv.w};
#pragma unroll
      for (int i = 0; i < 4; i++)
#pragma unroll
        for (int j = 0; j < 4; j++) acc[i][j] += am[i] * bm[j];
    }
    __syncthreads();
  }
#pragma unroll
  for (int i = 0; i < 4; i++) {
    int m = row0 + ty * 4 + i;
    int bb = m / NNODE;
    int n = m - bb * NNODE;
#pragma unroll
    for (int j = 0; j < 4; j++) {
      int col = col0 + tx * 4 + j;
      float v = acc[i][j] + bias[col];
      if (col < 256) {
        int h = col >> 5, dd = col & 31;
        d_K[(((size_t)bb * NH + h) * HDIM + dd) * NPAD + n] = v;
      } else if (col < 512) {
        int c = col - 256;
        int h = c >> 5, dd = c & 31;
        d_V[(((size_t)bb * NH + h) * HDIM + dd) * NPAD + n] = v;
      } else {
        d_L[((size_t)bb * DIM + (col - 512)) * NPAD + n] = v;
      }
    }
  }
}

// ---------------- per-step small GEMMs, 32x32 tiles -> 128 blocks ----------------
// mode 0: q = fixed + [ctx | ew_t] @ w_sc + b_sc           (K=768)
// mode 2: ctx += ([sel_emb | curr_emb] @ w_edge + b - ctx)/t   (K=512)
// Per-output: single accumulator, k strictly ascending (same order class as R4).
__global__ __launch_bounds__(256) void k_gemm(int mode, int t,
                                              const float* __restrict__ ne,
                                              const float* __restrict__ ew,
                                              const float* __restrict__ wmat,
                                              const float* __restrict__ bias,
                                              float tf) {
  __shared__ float As[16][33];   // [k][m]
  __shared__ float Bs[16][32];   // [k][n]
  int tid = threadIdx.x;
  int tx = tid & 15, ty = tid >> 4;          // 16x16 threads, 2x2 outputs each
  int row0 = blockIdx.x * 32;
  int col0 = blockIdx.y * 32;
  int ar = tid >> 3, ac2 = (tid & 7) * 2;    // A loader: row 0..31, k-pair
  int br = tid >> 4, bc2 = (tid & 15) * 2;   // B loader: k 0..15, col-pair
  int K = (mode == 0) ? 768 : 512;
  float acc[2][2] = {{0.f, 0.f}, {0.f, 0.f}};

  for (int k0 = 0; k0 < K; k0 += 16) {
    int m = row0 + ar;
    int kk = k0 + ac2;
    float2 av;
    if (mode == 0) {
      if (kk < 256)
        av = *(const float2*)&d_ctx[m * DIM + kk];
      else
        av = *(const float2*)&ew[((size_t)m * TSTEPS + t) * EWD + (kk - 256)];
    } else {
      if (kk < 256) {
        int s = d_sel[m];
        av = *(const float2*)&ne[((size_t)m * NNODE + s) * DIM + kk];
      } else {
        av = *(const float2*)&ne[((size_t)m * NNODE + (NNODE - 1)) * DIM + (kk - 256)];
      }
    }
    As[ac2 & 15][ar] = av.x;          // ac2 in {0,2,..,14}
    As[(ac2 & 15) + 1][ar] = av.y;
    float2 bv = *(const float2*)&wmat[(size_t)(k0 + br) * DIM + col0 + bc2];
    Bs[br][bc2] = bv.x;
    Bs[br][bc2 + 1] = bv.y;
    __syncthreads();
#pragma unroll
    for (int k = 0; k < 16; k++) {
      float a0 = As[k][ty * 2], a1 = As[k][ty * 2 + 1];
      float b0 = Bs[k][tx * 2], b1 = Bs[k][tx * 2 + 1];
      acc[0][0] = fmaf(a0, b0, acc[0][0]);
      acc[0][1] = fmaf(a0, b1, acc[0][1]);
      acc[1][0] = fmaf(a1, b0, acc[1][0]);
      acc[1][1] = fmaf(a1, b1, acc[1][1]);
    }
    __syncthreads();
  }
#pragma unroll
  for (int i = 0; i < 2; i++) {
    int m = row0 + ty * 2 + i;
#pragma unroll
    for (int j = 0; j < 2; j++) {
      int col = col0 + tx * 2 + j;
      float v = acc[i][j] + bias[col];
      if (mode == 0) {
        d_q[m * DIM + col] = v + d_fixed[m * DIM + col];
      } else {
        float old = d_ctx[m * DIM + col];
        d_ctx[m * DIM + col] = old + (v - old) / tf;
      }
    }
  }
}

// ---------------- streaming per-step kernel: one block per batch element ----------------
// attention (8 heads) -> glimpse -> logits -> log_softmax -> argmax -> output.
__global__ __launch_bounds__(512) void k_step2(float* __restrict__ out,
                                               const float* __restrict__ w_out,
                                               const float* __restrict__ b_out,
                                               int t) {
  int b = blockIdx.x;
  int tid = threadIdx.x, lane = tid & 31, w = tid >> 5;   // 16 warps
  __shared__ float s_q[DIM];
  __shared__ float s_at[NH][NPAD];
  __shared__ float s_heads[DIM];
  __shared__ float s_gp[2][DIM];
  __shared__ float s_g[DIM];
  __shared__ float s_l[NNODE];
  __shared__ unsigned char s_mask[NNODE];
  __shared__ float s_rm[16];
  __shared__ int s_ri[16];
  __shared__ float s_rs[16];

  if (tid < DIM) s_q[tid] = d_q[b * DIM + tid];
  for (int i = tid; i < NNODE; i += 512) s_mask[i] = d_mask[(size_t)b * NNODE + i];
  __syncthreads();

  // ---- compat: thread owns node tid; 8 per-head accumulators, d ascending per head ----
  const float* Kb = d_K + (size_t)b * NH * HDIM * NPAD;
  {
    float acc[NH];
#pragma unroll
    for (int h = 0; h < NH; ++h) acc[h] = 0.f;
#pragma unroll 4
    for (int d = 0; d < HDIM; ++d) {
      size_t off = (size_t)d * NPAD + tid;
#pragma unroll
      for (int h = 0; h < NH; ++h)
        acc[h] = fmaf(Kb[(size_t)h * HDIM * NPAD + off], s_q[h * HDIM + d], acc[h]);
    }
    unsigned char mk = s_mask[tid];
#pragma unroll
    for (int h = 0; h < NH; ++h) s_at[h][tid] = mk ? NEGV : acc[h] * INV_HD;
  }
  // node 512: 8 spread threads (one per head), d ascending
  if ((tid & 63) == 0) {
    int h = tid >> 6;
    const float* Kh = Kb + (size_t)h * HDIM * NPAD + 512;
    float a = 0.f;
#pragma unroll 8
    for (int d = 0; d < HDIM; ++d) a = fmaf(Kh[(size_t)d * NPAD], s_q[h * HDIM + d], a);
    s_at[h][512] = s_mask[512] ? NEGV : a * INV_HD;
  }
  __syncthreads();

  // ---- softmax per head: warp w < 8 handles head w ----
  if (w < NH) {
    float m = -3.402823466e38f;
    for (int i = lane; i < NNODE; i += 32) m = fmaxf(m, s_at[w][i]);
#pragma unroll
    for (int o = 16; o; o >>= 1) m = fmaxf(m, __shfl_xor_sync(0xffffffffu, m, o));
    float s = 0.f;
    for (int i = lane; i < NNODE; i += 32) {
      float e = expf(s_at[w][i] - m);
      s_at[w][i] = e;
      s += e;
    }
#pragma unroll
    for (int o = 16; o; o >>= 1) s += __shfl_xor_sync(0xffffffffu, s, o);
    float inv = 1.0f / s;
    for (int i = lane; i < NNODE; i += 32) s_at[w][i] *= inv;
  }
  __syncthreads();

  // ---- heads: warp w -> head w>>1, dims (w&1)*16..+16 ----
  {
    int h = w >> 1;
    int j0 = (w & 1) * 16;
    const float* Vh = d_V + ((size_t)b * NH + h) * HDIM * NPAD;
    for (int j = 0; j < 16; ++j) {
      const float* row = Vh + (size_t)(j0 + j) * NPAD;
      float acc = 0.f;
      for (int i = lane; i < NNODE; i += 32) acc += s_at[h][i] * row[i];
#pragma unroll
      for (int o = 16; o; o >>= 1) acc += __shfl_xor_sync(0xffffffffu, acc, o);
      if (lane == 0) s_heads[h * HDIM + j0 + j] = acc;
    }
  }
  __syncthreads();

  // ---- glimpse = heads @ w_out + b_out, split-K halves (R4-passing pattern) ----
  {
    int half = tid >> 8;        // 0 or 1
    int col = tid & 255;
    float g = (half == 0) ? b_out[col] : 0.f;
    int d0 = half * 128;
#pragma unroll 8
    for (int d = 0; d < 128; ++d)
      g = fmaf(s_heads[d0 + d], w_out[(size_t)(d0 + d) * DIM + col], g);
    s_gp[half][col] = g;
  }
  __syncthreads();
  if (tid < DIM) s_g[tid] = s_gp[0][tid] + s_gp[1][tid];
  __syncthreads();

  // ---- logits = tanh10(glimpse . L_n / 16), masked; thread owns node tid ----
  {
    const float* Lb = d_L + (size_t)b * DIM * NPAD;
    float a0 = 0.f;
#pragma unroll 8
    for (int d = 0; d < DIM; ++d)
      a0 = fmaf(Lb[(size_t)d * NPAD + tid], s_g[d], a0);
    s_l[tid] = s_mask[tid] ? NEGV : tanh10(a0 * INV_D);
  }
  // node 512: warp 15 lane-strided dot + shuffle tree
  if (w == 15) {
    const float* Lb = d_L + (size_t)b * DIM * NPAD + 512;
    float a = 0.f;
#pragma unroll
    for (int j = 0; j < DIM / 32; ++j)
      a = fmaf(Lb[(size_t)(j * 32 + lane) * NPAD], s_g[j * 32 + lane], a);
#pragma unroll
    for (int o = 16; o; o >>= 1) a += __shfl_xor_sync(0xffffffffu, a, o);
    if (lane == 0) s_l[512] = s_mask[512] ? NEGV : tanh10(a * INV_D);
  }
  __syncthreads();

  // ---- argmax (first occurrence on ties) ----
  float m = -3.402823466e38f;
  int mi = NNODE;
  for (int i = tid; i < NNODE; i += 512) {
    float v = s_l[i];
    if (v > m) { m = v; mi = i; }
  }
#pragma unroll
  for (int o = 16; o; o >>= 1) {
    float om = __shfl_xor_sync(0xffffffffu, m, o);
    int oi = __shfl_xor_sync(0xffffffffu, mi, o);
    if (om > m || (om == m && oi < mi)) { m = om; mi = oi; }
  }
  if (lane == 0) { s_rm[w] = m; s_ri[w] = mi; }
  __syncthreads();
  float mm = s_rm[0];
  int bi = s_ri[0];
#pragma unroll
  for (int i = 1; i < 16; i++) {
    if (s_rm[i] > mm || (s_rm[i] == mm && s_ri[i] < bi)) { mm = s_rm[i]; bi = s_ri[i]; }
  }

  // ---- logsumexp ----
  float s = 0.f;
  for (int i = tid; i < NNODE; i += 512) s += expf(s_l[i] - mm);
#pragma unroll
  for (int o = 16; o; o >>= 1) s += __shfl_xor_sync(0xffffffffu, s, o);
  if (lane == 0) s_rs[w] = s;
  __syncthreads();
  float ss = s_rs[0];
#pragma unroll
  for (int i = 1; i < 16; i++) ss += s_rs[i];
  float lse = mm + logf(ss);

  float* ob = out + ((size_t)b * TSTEPS + t) * NNODE;
  for (int i = tid; i < NNODE; i += 512) ob[i] = s_l[i] - lse;
  if (tid == 0) {
    d_sel[b] = bi;
    if (bi > 0) d_mask[(size_t)b * NNODE + bi] = 1;
  }
}

// ---------------- launch ----------------
extern "C" void kernel_launch(void* const* d_in, const int* in_sizes, int n_in,
                              void* d_out, int out_size) {
  const float* ne     = (const float*)d_in[0];   // (B, N, D)
  const float* ew     = (const float*)d_in[1];   // (B, T, U+1)
  const float* w_kvl  = (const float*)d_in[2];   // (D, 3D)
  const float* b_kvl  = (const float*)d_in[3];
  const float* w_fc   = (const float*)d_in[4];   // (D, D)
  const float* b_fc   = (const float*)d_in[5];
  const float* w_sc   = (const float*)d_in[6];   // (768, D)
  const float* b_sc   = (const float*)d_in[7];
  const float* w_out  = (const float*)d_in[8];   // (D, D)
  const float* b_out  = (const float*)d_in[9];
  const float* w_edge = (const float*)d_in[10];  // (2D, D)
  const float* b_edge = (const float*)d_in[11];
  float* out = (float*)d_out;

  k_precompute_fixed<<<BATCH, 256>>>(ne, w_fc, b_fc);
  k_kvl<<<dim3((BATCH * NNODE) / 64, 768 / 64), 256>>>(ne, w_kvl, b_kvl);

  dim3 gg(BATCH / 32, DIM / 32);   // 16 x 8 = 128 blocks
  for (int t = 0; t < TSTEPS; ++t) {
    k_gemm<<<gg, 256>>>(0, t, ne, ew, w_sc, b_sc, 0.f);
    k_step2<<<BATCH, 512>>>(out, w_out, b_out, t);
    k_gemm<<<gg, 256>>>(2, t, ne, ew, w_edge, b_edge, (float)(t + 1));
  }
}

// round 15
// speedup vs baseline: 1.4816x; 1.0504x over previous
#include <cuda_runtime.h>
#include <math.h>

#define BATCH 512
#define NNODE 513
#define NPAD  520          // padded node stride
#define DIM   256
#define NH    8
#define HDIM  32
#define TSTEPS 128
#define EWD   512          // U+1
#define NEGV  -1000000000.0f
#define INV_HD 0.176776695296636893f   // 1/sqrt(32)
#define INV_D  0.0625f                 // 1/sqrt(256)

// ---------------- static device scratch ----------------
// Transposed layouts: K,V = (b, h, d, n_pad)   L = (b, d, n_pad)
static __device__ float d_K[(size_t)BATCH * NH * HDIM * NPAD];
static __device__ float d_V[(size_t)BATCH * NH * HDIM * NPAD];
static __device__ float d_L[(size_t)BATCH * DIM * NPAD];
static __device__ float d_fixed[BATCH * DIM];
static __device__ float d_ctx[BATCH * DIM];      // exact reference recursion space
static __device__ float d_q[BATCH * DIM];
static __device__ int d_sel[BATCH];
static __device__ unsigned char d_mask[BATCH * NNODE];

// 10*tanh(x) via expf so fast-math __tanhf can't perturb the argmax chain.
__device__ __forceinline__ float tanh10(float x) {
  float ax = fabsf(x);
  float t = expf(-2.0f * ax);
  float r = (1.0f - t) / (1.0f + t);
  return copysignf(10.0f * r, x);
}

// ---------------- precompute: graph mean -> fixed_ctx; init state ----------------
__global__ void k_precompute_fixed(const float* __restrict__ ne,
                                   const float* __restrict__ w_fc,
                                   const float* __restrict__ b_fc) {
  int b = blockIdx.x, tid = threadIdx.x;
  __shared__ float mean[DIM];
  const float* base = ne + (size_t)b * NNODE * DIM;
  float acc = 0.f;
  for (int n = 0; n < NNODE; ++n) acc += base[(size_t)n * DIM + tid];
  mean[tid] = acc / (float)NNODE;
  __syncthreads();
  float o = b_fc[tid];
  for (int d = 0; d < DIM; ++d) o += mean[d] * w_fc[d * DIM + tid];
  d_fixed[b * DIM + tid] = o;
  d_ctx[b * DIM + tid] = 0.f;
  for (int i = tid; i < NNODE; i += 256) d_mask[(size_t)b * NNODE + i] = 0;
}

// ---------------- precompute: KVL = node_embeds @ w_kvl + b, scattered transposed ----------------
__global__ void k_kvl(const float* __restrict__ ne,
                      const float* __restrict__ w,
                      const float* __restrict__ bias) {
  __shared__ float As[16][72];
  __shared__ float Bs[16][64];
  int tid = threadIdx.x;
  int tx = tid & 15, ty = tid >> 4;
  int row0 = blockIdx.x * 64;
  int col0 = blockIdx.y * 64;
  int ar = tid >> 2, ac4 = tid & 3;
  int br = tid >> 4, bc4 = tid & 15;
  float acc[4][4];
#pragma unroll
  for (int i = 0; i < 4; i++)
#pragma unroll
    for (int j = 0; j < 4; j++) acc[i][j] = 0.f;

  for (int k0 = 0; k0 < DIM; k0 += 16) {
    float4 av = *(const float4*)&ne[(size_t)(row0 + ar) * DIM + k0 + ac4 * 4];
    As[ac4 * 4 + 0][ar] = av.x;
    As[ac4 * 4 + 1][ar] = av.y;
    As[ac4 * 4 + 2][ar] = av.z;
    As[ac4 * 4 + 3][ar] = av.w;
    *(float4*)&Bs[br][bc4 * 4] =
        *(const float4*)&w[(size_t)(k0 + br) * 768 + col0 + bc4 * 4];
    __syncthreads();
#pragma unroll
    for (int k = 0; k < 16; k++) {
      float4 a = *(const float4*)&As[k][ty * 4];
      float4 bv = *(const float4*)&Bs[k][tx * 4];
      float am[4] = {a.x, a.y, a.z, a.w};
      float bm[4] = {bv.x, bv.y, bv.z, bv.w};
#pragma unroll
      for (int i = 0; i < 4; i++)
#pragma unroll
        for (int j = 0; j < 4; j++) acc[i][j] += am[i] * bm[j];
    }
    __syncthreads();
  }
#pragma unroll
  for (int i = 0; i < 4; i++) {
    int m = row0 + ty * 4 + i;
    int bb = m / NNODE;
    int n = m - bb * NNODE;
#pragma unroll
    for (int j = 0; j < 4; j++) {
      int col = col0 + tx * 4 + j;
      float v = acc[i][j] + bias[col];
      if (col < 256) {
        int h = col >> 5, dd = col & 31;
        d_K[(((size_t)bb * NH + h) * HDIM + dd) * NPAD + n] = v;
      } else if (col < 512) {
        int c = col - 256;
        int h = c >> 5, dd = c & 31;
        d_V[(((size_t)bb * NH + h) * HDIM + dd) * NPAD + n] = v;
      } else {
        d_L[((size_t)bb * DIM + (col - 512)) * NPAD + n] = v;
      }
    }
  }
}

// ---------------- per-step small GEMMs, 32x32 tiles, double-buffered ----------------
// mode 0: q = fixed + [ctx | ew_t] @ w_sc + b_sc              (K=768)
// mode 2: ctx += ([sel_emb | curr_emb] @ w_edge + b - ctx)/t  (K=512)
// Per-output: single accumulator, k strictly ascending (unchanged arithmetic).
__global__ __launch_bounds__(256) void k_gemm(int mode, int t,
                                              const float* __restrict__ ne,
                                              const float* __restrict__ ew,
                                              const float* __restrict__ wmat,
                                              const float* __restrict__ bias,
                                              float tf) {
  __shared__ float As[2][16][33];   // [buf][k][m]
  __shared__ float Bs[2][16][32];   // [buf][k][n]
  int tid = threadIdx.x;
  int tx = tid & 15, ty = tid >> 4;          // 16x16 threads, 2x2 outputs each
  int row0 = blockIdx.x * 32;
  int col0 = blockIdx.y * 32;
  int ar = tid >> 3, ac2 = (tid & 7) * 2;    // A loader: row 0..31, k-pair
  int br = tid >> 4, bc2 = (tid & 15) * 2;   // B loader: k 0..15, col-pair
  int K = (mode == 0) ? 768 : 512;
  int m = row0 + ar;
  float acc[2][2] = {{0.f, 0.f}, {0.f, 0.f}};

  // A-tile fetch into registers for k-base k0
  auto loadA = [&](int k0) -> float2 {
    int kk = k0 + ac2;
    if (mode == 0) {
      if (kk < 256) return *(const float2*)&d_ctx[m * DIM + kk];
      return *(const float2*)&ew[((size_t)m * TSTEPS + t) * EWD + (kk - 256)];
    } else {
      if (kk < 256) {
        int s = d_sel[m];
        return *(const float2*)&ne[((size_t)m * NNODE + s) * DIM + kk];
      }
      return *(const float2*)&ne[((size_t)m * NNODE + (NNODE - 1)) * DIM + (kk - 256)];
    }
  };

  // prologue: tile 0 -> buffer 0
  float2 a_reg = loadA(0);
  float2 b_reg = *(const float2*)&wmat[(size_t)br * DIM + col0 + bc2];
  As[0][ac2][ar] = a_reg.x;
  As[0][ac2 + 1][ar] = a_reg.y;
  Bs[0][br][bc2] = b_reg.x;
  Bs[0][br][bc2 + 1] = b_reg.y;
  __syncthreads();

  int p = 0;
  for (int k0 = 0; k0 < K; k0 += 16) {
    int nk = k0 + 16;
    bool more = (nk < K);
    if (more) {
      a_reg = loadA(nk);
      b_reg = *(const float2*)&wmat[(size_t)(nk + br) * DIM + col0 + bc2];
    }
#pragma unroll
    for (int k = 0; k < 16; k++) {
      float a0 = As[p][k][ty * 2], a1 = As[p][k][ty * 2 + 1];
      float b0 = Bs[p][k][tx * 2], b1 = Bs[p][k][tx * 2 + 1];
      acc[0][0] = fmaf(a0, b0, acc[0][0]);
      acc[0][1] = fmaf(a0, b1, acc[0][1]);
      acc[1][0] = fmaf(a1, b0, acc[1][0]);
      acc[1][1] = fmaf(a1, b1, acc[1][1]);
    }
    if (more) {
      As[1 - p][ac2][ar] = a_reg.x;
      As[1 - p][ac2 + 1][ar] = a_reg.y;
      Bs[1 - p][br][bc2] = b_reg.x;
      Bs[1 - p][br][bc2 + 1] = b_reg.y;
    }
    __syncthreads();
    p ^= 1;
  }
#pragma unroll
  for (int i = 0; i < 2; i++) {
    int mm = row0 + ty * 2 + i;
#pragma unroll
    for (int j = 0; j < 2; j++) {
      int col = col0 + tx * 2 + j;
      float v = acc[i][j] + bias[col];
      if (mode == 0) {
        d_q[mm * DIM + col] = v + d_fixed[mm * DIM + col];
      } else {
        float old = d_ctx[mm * DIM + col];
        d_ctx[mm * DIM + col] = old + (v - old) / tf;
      }
    }
  }
}

// ---------------- streaming per-step kernel: one block per batch element ----------------
// attention (8 heads) -> glimpse -> logits -> log_softmax -> argmax -> output.
__global__ __launch_bounds__(512) void k_step2(float* __restrict__ out,
                                               const float* __restrict__ w_out,
                                               const float* __restrict__ b_out,
                                               int t) {
  int b = blockIdx.x;
  int tid = threadIdx.x, lane = tid & 31, w = tid >> 5;   // 16 warps
  __shared__ float s_q[DIM];
  __shared__ float s_at[NH][NPAD];
  __shared__ float s_heads[DIM];
  __shared__ float s_gp[2][DIM];
  __shared__ float s_g[DIM];
  __shared__ float s_l[NNODE];
  __shared__ unsigned char s_mask[NNODE];
  __shared__ float s_rm[16];
  __shared__ int s_ri[16];
  __shared__ float s_rs[16];

  if (tid < DIM) s_q[tid] = d_q[b * DIM + tid];
  for (int i = tid; i < NNODE; i += 512) s_mask[i] = d_mask[(size_t)b * NNODE + i];
  __syncthreads();

  // ---- compat: thread owns node tid; 8 per-head accumulators, d ascending per head ----
  const float* Kb = d_K + (size_t)b * NH * HDIM * NPAD;
  {
    float acc[NH];
#pragma unroll
    for (int h = 0; h < NH; ++h) acc[h] = 0.f;
#pragma unroll 4
    for (int d = 0; d < HDIM; ++d) {
      size_t off = (size_t)d * NPAD + tid;
#pragma unroll
      for (int h = 0; h < NH; ++h)
        acc[h] = fmaf(Kb[(size_t)h * HDIM * NPAD + off], s_q[h * HDIM + d], acc[h]);
    }
    unsigned char mk = s_mask[tid];
#pragma unroll
    for (int h = 0; h < NH; ++h) s_at[h][tid] = mk ? NEGV : acc[h] * INV_HD;
  }
  // node 512: 8 spread threads (one per head), d ascending
  if ((tid & 63) == 0) {
    int h = tid >> 6;
    const float* Kh = Kb + (size_t)h * HDIM * NPAD + 512;
    float a = 0.f;
#pragma unroll 8
    for (int d = 0; d < HDIM; ++d) a = fmaf(Kh[(size_t)d * NPAD], s_q[h * HDIM + d], a);
    s_at[h][512] = s_mask[512] ? NEGV : a * INV_HD;
  }
  __syncthreads();

  // ---- softmax per head: warp w < 8 handles head w ----
  if (w < NH) {
    float m = -3.402823466e38f;
    for (int i = lane; i < NNODE; i += 32) m = fmaxf(m, s_at[w][i]);
#pragma unroll
    for (int o = 16; o; o >>= 1) m = fmaxf(m, __shfl_xor_sync(0xffffffffu, m, o));
    float s = 0.f;
    for (int i = lane; i < NNODE; i += 32) {
      float e = expf(s_at[w][i] - m);
      s_at[w][i] = e;
      s += e;
    }
#pragma unroll
    for (int o = 16; o; o >>= 1) s += __shfl_xor_sync(0xffffffffu, s, o);
    float inv = 1.0f / s;
    for (int i = lane; i < NNODE; i += 32) s_at[w][i] *= inv;
  }
  __syncthreads();

  // ---- heads: warp w -> head w>>1, dims (w&1)*16..+16, 16 interleaved accumulators ----
  // Per-output arithmetic identical to before: lane accumulates i = lane, lane+32, ...
  // ascending, then the same shuffle tree. Interleaving dims only raises MLP.
  {
    int h = w >> 1;
    int j0 = (w & 1) * 16;
    const float* Vh = d_V + ((size_t)b * NH + h) * HDIM * NPAD + (size_t)j0 * NPAD;
    float acc[16];
#pragma unroll
    for (int j = 0; j < 16; ++j) acc[j] = 0.f;
    for (int i = lane; i < NNODE; i += 32) {
      float a = s_at[h][i];
#pragma unroll
      for (int j = 0; j < 16; ++j)
        acc[j] = fmaf(a, Vh[(size_t)j * NPAD + i], acc[j]);
    }
#pragma unroll
    for (int j = 0; j < 16; ++j) {
      float v = acc[j];
#pragma unroll
      for (int o = 16; o; o >>= 1) v += __shfl_xor_sync(0xffffffffu, v, o);
      if (lane == 0) s_heads[h * HDIM + j0 + j] = v;
    }
  }
  __syncthreads();

  // ---- glimpse = heads @ w_out + b_out, split-K halves (passing pattern) ----
  {
    int half = tid >> 8;        // 0 or 1
    int col = tid & 255;
    float g = (half == 0) ? b_out[col] : 0.f;
    int d0 = half * 128;
#pragma unroll 8
    for (int d = 0; d < 128; ++d)
      g = fmaf(s_heads[d0 + d], w_out[(size_t)(d0 + d) * DIM + col], g);
    s_gp[half][col] = g;
  }
  __syncthreads();
  if (tid < DIM) s_g[tid] = s_gp[0][tid] + s_gp[1][tid];
  __syncthreads();

  // ---- logits = tanh10(glimpse . L_n / 16), masked; thread owns node tid ----
  {
    const float* Lb = d_L + (size_t)b * DIM * NPAD;
    float a0 = 0.f;
#pragma unroll 8
    for (int d = 0; d < DIM; ++d)
      a0 = fmaf(Lb[(size_t)d * NPAD + tid], s_g[d], a0);
    s_l[tid] = s_mask[tid] ? NEGV : tanh10(a0 * INV_D);
  }
  // node 512: warp 15 lane-strided dot + shuffle tree
  if (w == 15) {
    const float* Lb = d_L + (size_t)b * DIM * NPAD + 512;
    float a = 0.f;
#pragma unroll
    for (int j = 0; j < DIM / 32; ++j)
      a = fmaf(Lb[(size_t)(j * 32 + lane) * NPAD], s_g[j * 32 + lane], a);
#pragma unroll
    for (int o = 16; o; o >>= 1) a += __shfl_xor_sync(0xffffffffu, a, o);
    if (lane == 0) s_l[512] = s_mask[512] ? NEGV : tanh10(a * INV_D);
  }
  __syncthreads();

  // ---- argmax (first occurrence on ties) ----
  float m = -3.402823466e38f;
  int mi = NNODE;
  for (int i = tid; i < NNODE; i += 512) {
    float v = s_l[i];
    if (v > m) { m = v; mi = i; }
  }
#pragma unroll
  for (int o = 16; o; o >>= 1) {
    float om = __shfl_xor_sync(0xffffffffu, m, o);
    int oi = __shfl_xor_sync(0xffffffffu, mi, o);
    if (om > m || (om == m && oi < mi)) { m = om; mi = oi; }
  }
  if (lane == 0) { s_rm[w] = m; s_ri[w] = mi; }
  __syncthreads();
  float mm = s_rm[0];
  int bi = s_ri[0];
#pragma unroll
  for (int i = 1; i < 16; i++) {
    if (s_rm[i] > mm || (s_rm[i] == mm && s_ri[i] < bi)) { mm = s_rm[i]; bi = s_ri[i]; }
  }

  // ---- logsumexp ----
  float s = 0.f;
  for (int i = tid; i < NNODE; i += 512) s += expf(s_l[i] - mm);
#pragma unroll
  for (int o = 16; o; o >>= 1) s += __shfl_xor_sync(0xffffffffu, s, o);
  if (lane == 0) s_rs[w] = s;
  __syncthreads();
  float ss = s_rs[0];
#pragma unroll
  for (int i = 1; i < 16; i++) ss += s_rs[i];
  float lse = mm + logf(ss);

  float* ob = out + ((size_t)b * TSTEPS + t) * NNODE;
  for (int i = tid; i < NNODE; i += 512) ob[i] = s_l[i] - lse;
  if (tid == 0) {
    d_sel[b] = bi;
    if (bi > 0) d_mask[(size_t)b * NNODE + bi] = 1;
  }
}

// ---------------- launch ----------------
extern "C" void kernel_launch(void* const* d_in, const int* in_sizes, int n_in,
                              void* d_out, int out_size) {
  const float* ne     = (const float*)d_in[0];   // (B, N, D)
  const float* ew     = (const float*)d_in[1];   // (B, T, U+1)
  const float* w_kvl  = (const float*)d_in[2];   // (D, 3D)
  const float* b_kvl  = (const float*)d_in[3];
  const float* w_fc   = (const float*)d_in[4];   // (D, D)
  const float* b_fc   = (const float*)d_in[5];
  const float* w_sc   = (const float*)d_in[6];   // (768, D)
  const float* b_sc   = (const float*)d_in[7];
  const float* w_out  = (const float*)d_in[8];   // (D, D)
  const float* b_out  = (const float*)d_in[9];
  const float* w_edge = (const float*)d_in[10];  // (2D, D)
  const float* b_edge = (const float*)d_in[11];
  float* out = (float*)d_out;

  k_precompute_fixed<<<BATCH, 256>>>(ne, w_fc, b_fc);
  k_kvl<<<dim3((BATCH * NNODE) / 64, 768 / 64), 256>>>(ne, w_kvl, b_kvl);

  dim3 gg(BATCH / 32, DIM / 32);   // 16 x 8 = 128 blocks
  for (int t = 0; t < TSTEPS; ++t) {
    k_gemm<<<gg, 256>>>(0, t, ne, ew, w_sc, b_sc, 0.f);
    k_step2<<<BATCH, 512>>>(out, w_out, b_out, t);
    k_gemm<<<gg, 256>>>(2, t, ne, ew, w_edge, b_edge, (float)(t + 1));
  }
}

// round 16
// speedup vs baseline: 1.7061x; 1.1515x over previous
#include <cuda_runtime.h>
#include <math.h>

#define BATCH 512
#define NNODE 513
#define NPAD  520          // padded node stride
#define DIM   256
#define NH    8
#define HDIM  32
#define TSTEPS 128
#define EWD   512          // U+1
#define NEGV  -1000000000.0f
#define INV_HD 0.176776695296636893f   // 1/sqrt(32)
#define INV_D  0.0625f                 // 1/sqrt(256)

// ---------------- static device scratch ----------------
// Transposed layouts: K,V = (b, h, d, n_pad)   L = (b, d, n_pad)
static __device__ float d_K[(size_t)BATCH * NH * HDIM * NPAD];
static __device__ float d_V[(size_t)BATCH * NH * HDIM * NPAD];
static __device__ float d_L[(size_t)BATCH * DIM * NPAD];
static __device__ float d_fixed[BATCH * DIM];
static __device__ float d_ctx[BATCH * DIM];      // exact reference recursion space
static __device__ float d_q[BATCH * DIM];
static __device__ float d_heads[BATCH * DIM];
static __device__ int d_sel[BATCH];
static __device__ unsigned char d_mask[BATCH * NNODE];

// 10*tanh(x) via expf so fast-math __tanhf can't perturb the argmax chain.
__device__ __forceinline__ float tanh10(float x) {
  float ax = fabsf(x);
  float t = expf(-2.0f * ax);
  float r = (1.0f - t) / (1.0f + t);
  return copysignf(10.0f * r, x);
}

// ---------------- precompute: graph mean -> fixed_ctx; init state ----------------
__global__ void k_precompute_fixed(const float* __restrict__ ne,
                                   const float* __restrict__ w_fc,
                                   const float* __restrict__ b_fc) {
  int b = blockIdx.x, tid = threadIdx.x;
  __shared__ float mean[DIM];
  const float* base = ne + (size_t)b * NNODE * DIM;
  float acc = 0.f;
  for (int n = 0; n < NNODE; ++n) acc += base[(size_t)n * DIM + tid];
  mean[tid] = acc / (float)NNODE;
  __syncthreads();
  float o = b_fc[tid];
  for (int d = 0; d < DIM; ++d) o += mean[d] * w_fc[d * DIM + tid];
  d_fixed[b * DIM + tid] = o;
  d_ctx[b * DIM + tid] = 0.f;
  for (int i = tid; i < NNODE; i += 256) d_mask[(size_t)b * NNODE + i] = 0;
}

// ---------------- precompute: KVL = node_embeds @ w_kvl + b, scattered transposed ----------------
__global__ void k_kvl(const float* __restrict__ ne,
                      const float* __restrict__ w,
                      const float* __restrict__ bias) {
  __shared__ float As[16][72];
  __shared__ float Bs[16][64];
  int tid = threadIdx.x;
  int tx = tid & 15, ty = tid >> 4;
  int row0 = blockIdx.x * 64;
  int col0 = blockIdx.y * 64;
  int ar = tid >> 2, ac4 = tid & 3;
  int br = tid >> 4, bc4 = tid & 15;
  float acc[4][4];
#pragma unroll
  for (int i = 0; i < 4; i++)
#pragma unroll
    for (int j = 0; j < 4; j++) acc[i][j] = 0.f;

  for (int k0 = 0; k0 < DIM; k0 += 16) {
    float4 av = *(const float4*)&ne[(size_t)(row0 + ar) * DIM + k0 + ac4 * 4];
    As[ac4 * 4 + 0][ar] = av.x;
    As[ac4 * 4 + 1][ar] = av.y;
    As[ac4 * 4 + 2][ar] = av.z;
    As[ac4 * 4 + 3][ar] = av.w;
    *(float4*)&Bs[br][bc4 * 4] =
        *(const float4*)&w[(size_t)(k0 + br) * 768 + col0 + bc4 * 4];
    __syncthreads();
#pragma unroll
    for (int k = 0; k < 16; k++) {
      float4 a = *(const float4*)&As[k][ty * 4];
      float4 bv = *(const float4*)&Bs[k][tx * 4];
      float am[4] = {a.x, a.y, a.z, a.w};
      float bm[4] = {bv.x, bv.y, bv.z, bv.w};
#pragma unroll
      for (int i = 0; i < 4; i++)
#pragma unroll
        for (int j = 0; j < 4; j++) acc[i][j] += am[i] * bm[j];
    }
    __syncthreads();
  }
#pragma unroll
  for (int i = 0; i < 4; i++) {
    int m = row0 + ty * 4 + i;
    int bb = m / NNODE;
    int n = m - bb * NNODE;
#pragma unroll
    for (int j = 0; j < 4; j++) {
      int col = col0 + tx * 4 + j;
      float v = acc[i][j] + bias[col];
      if (col < 256) {
        int h = col >> 5, dd = col & 31;
        d_K[(((size_t)bb * NH + h) * HDIM + dd) * NPAD + n] = v;
      } else if (col < 512) {
        int c = col - 256;
        int h = c >> 5, dd = c & 31;
        d_V[(((size_t)bb * NH + h) * HDIM + dd) * NPAD + n] = v;
      } else {
        d_L[((size_t)bb * DIM + (col - 512)) * NPAD + n] = v;
      }
    }
  }
}

// ---------------- per-step small GEMMs, 32x32 tiles, double-buffered ----------------
// mode 0: q = fixed + [ctx | ew_t] @ w_sc + b_sc              (K=768)
// mode 2: ctx += ([sel_emb | curr_emb] @ w_edge + b - ctx)/t  (K=512)
__global__ __launch_bounds__(256) void k_gemm(int mode, int t,
                                              const float* __restrict__ ne,
                                              const float* __restrict__ ew,
                                              const float* __restrict__ wmat,
                                              const float* __restrict__ bias,
                                              float tf) {
  __shared__ float As[2][16][33];   // [buf][k][m]
  __shared__ float Bs[2][16][32];   // [buf][k][n]
  int tid = threadIdx.x;
  int tx = tid & 15, ty = tid >> 4;
  int row0 = blockIdx.x * 32;
  int col0 = blockIdx.y * 32;
  int ar = tid >> 3, ac2 = (tid & 7) * 2;
  int br = tid >> 4, bc2 = (tid & 15) * 2;
  int K = (mode == 0) ? 768 : 512;
  int m = row0 + ar;
  float acc[2][2] = {{0.f, 0.f}, {0.f, 0.f}};

  auto loadA = [&](int k0) -> float2 {
    int kk = k0 + ac2;
    if (mode == 0) {
      if (kk < 256) return *(const float2*)&d_ctx[m * DIM + kk];
      return *(const float2*)&ew[((size_t)m * TSTEPS + t) * EWD + (kk - 256)];
    } else {
      if (kk < 256) {
        int s = d_sel[m];
        return *(const float2*)&ne[((size_t)m * NNODE + s) * DIM + kk];
      }
      return *(const float2*)&ne[((size_t)m * NNODE + (NNODE - 1)) * DIM + (kk - 256)];
    }
  };

  float2 a_reg = loadA(0);
  float2 b_reg = *(const float2*)&wmat[(size_t)br * DIM + col0 + bc2];
  As[0][ac2][ar] = a_reg.x;
  As[0][ac2 + 1][ar] = a_reg.y;
  Bs[0][br][bc2] = b_reg.x;
  Bs[0][br][bc2 + 1] = b_reg.y;
  __syncthreads();

  int p = 0;
  for (int k0 = 0; k0 < K; k0 += 16) {
    int nk = k0 + 16;
    bool more = (nk < K);
    if (more) {
      a_reg = loadA(nk);
      b_reg = *(const float2*)&wmat[(size_t)(nk + br) * DIM + col0 + bc2];
    }
#pragma unroll
    for (int k = 0; k < 16; k++) {
      float a0 = As[p][k][ty * 2], a1 = As[p][k][ty * 2 + 1];
      float b0 = Bs[p][k][tx * 2], b1 = Bs[p][k][tx * 2 + 1];
      acc[0][0] = fmaf(a0, b0, acc[0][0]);
      acc[0][1] = fmaf(a0, b1, acc[0][1]);
      acc[1][0] = fmaf(a1, b0, acc[1][0]);
      acc[1][1] = fmaf(a1, b1, acc[1][1]);
    }
    if (more) {
      As[1 - p][ac2][ar] = a_reg.x;
      As[1 - p][ac2 + 1][ar] = a_reg.y;
      Bs[1 - p][br][bc2] = b_reg.x;
      Bs[1 - p][br][bc2 + 1] = b_reg.y;
    }
    __syncthreads();
    p ^= 1;
  }
#pragma unroll
  for (int i = 0; i < 2; i++) {
    int mm = row0 + ty * 2 + i;
#pragma unroll
    for (int j = 0; j < 2; j++) {
      int col = col0 + tx * 2 + j;
      float v = acc[i][j] + bias[col];
      if (mode == 0) {
        d_q[mm * DIM + col] = v + d_fixed[mm * DIM + col];
      } else {
        float old = d_ctx[mm * DIM + col];
        d_ctx[mm * DIM + col] = old + (v - old) / tf;
      }
    }
  }
}

// ---------------- per-(b,h) attention kernel: compat -> softmax -> heads ----------------
// grid (NH, BATCH), 256 threads. Pure streaming of K_h then V_h with a tiny smem
// softmax in between; 4096 blocks keep DRAM saturated.
__global__ __launch_bounds__(256) void k_attn(int t) {
  int h = blockIdx.x, b = blockIdx.y;
  int tid = threadIdx.x, lane = tid & 31, w = tid >> 5;   // 8 warps
  __shared__ float s_q[HDIM];
  __shared__ float s_at[NNODE];
  __shared__ float s_red[8];

  if (tid < HDIM) s_q[tid] = d_q[b * DIM + h * HDIM + tid];
  __syncthreads();

  const unsigned char* mk = d_mask + (size_t)b * NNODE;
  const float* Kh = d_K + ((size_t)(b * NH + h) * HDIM) * NPAD;

  // ---- compat: thread owns nodes tid, tid+256 (tid 0 also 512), d ascending ----
  {
    float a0 = 0.f, a1 = 0.f, a2 = 0.f;
#pragma unroll 8
    for (int d = 0; d < HDIM; ++d) {
      float qv = s_q[d];
      const float* row = Kh + (size_t)d * NPAD;
      a0 = fmaf(row[tid], qv, a0);
      a1 = fmaf(row[tid + 256], qv, a1);
      if (tid == 0) a2 = fmaf(row[512], qv, a2);
    }
    s_at[tid]       = mk[tid]       ? NEGV : a0 * INV_HD;
    s_at[tid + 256] = mk[tid + 256] ? NEGV : a1 * INV_HD;
    if (tid == 0) s_at[512] = mk[512] ? NEGV : a2 * INV_HD;
  }
  __syncthreads();

  // ---- block softmax over 513 (max is order-exact; sum reorder is 1e-7-safe) ----
  float m = fmaxf(s_at[tid], s_at[tid + 256]);
  if (tid == 0) m = fmaxf(m, s_at[512]);
#pragma unroll
  for (int o = 16; o; o >>= 1) m = fmaxf(m, __shfl_xor_sync(0xffffffffu, m, o));
  if (lane == 0) s_red[w] = m;
  __syncthreads();
  float mm = s_red[0];
#pragma unroll
  for (int i = 1; i < 8; i++) mm = fmaxf(mm, s_red[i]);
  __syncthreads();

  float e0 = expf(s_at[tid] - mm);
  float e1 = expf(s_at[tid + 256] - mm);
  s_at[tid] = e0;
  s_at[tid + 256] = e1;
  float s = e0 + e1;
  if (tid == 0) {
    float e2 = expf(s_at[512] - mm);
    s_at[512] = e2;
    s += e2;
  }
#pragma unroll
  for (int o = 16; o; o >>= 1) s += __shfl_xor_sync(0xffffffffu, s, o);
  __syncthreads();          // protect s_red reuse
  if (lane == 0) s_red[w] = s;
  __syncthreads();
  float ss = s_red[0];
#pragma unroll
  for (int i = 1; i < 8; i++) ss += s_red[i];
  float inv = 1.0f / ss;
  s_at[tid] *= inv;
  s_at[tid + 256] *= inv;
  if (tid == 0) s_at[512] *= inv;
  __syncthreads();

  // ---- heads: warp w -> dims w*4..w*4+3, 4 interleaved lane-stride-32 dots ----
  {
    const float* Vh = d_V + ((size_t)(b * NH + h) * HDIM) * NPAD + (size_t)(w * 4) * NPAD;
    float acc[4] = {0.f, 0.f, 0.f, 0.f};
    for (int i = lane; i < NNODE; i += 32) {
      float a = s_at[i];
#pragma unroll
      for (int j = 0; j < 4; ++j) acc[j] = fmaf(a, Vh[(size_t)j * NPAD + i], acc[j]);
    }
#pragma unroll
    for (int j = 0; j < 4; ++j) {
      float v = acc[j];
#pragma unroll
      for (int o = 16; o; o >>= 1) v += __shfl_xor_sync(0xffffffffu, v, o);
      if (lane == 0) d_heads[b * DIM + h * HDIM + w * 4 + j] = v;
    }
  }
}

// ---------------- per-b finish kernel: glimpse -> logits -> argmax -> output ----------------
__global__ __launch_bounds__(512) void k_fin(float* __restrict__ out,
                                             const float* __restrict__ w_out,
                                             const float* __restrict__ b_out,
                                             int t) {
  int b = blockIdx.x;
  int tid = threadIdx.x, lane = tid & 31, w = tid >> 5;   // 16 warps
  __shared__ float s_heads[DIM];
  __shared__ float s_gp[2][DIM];
  __shared__ float s_g[DIM];
  __shared__ float s_l[NNODE];
  __shared__ unsigned char s_mask[NNODE];
  __shared__ float s_rm[16];
  __shared__ int s_ri[16];
  __shared__ float s_rs[16];

  if (tid < DIM) s_heads[tid] = d_heads[b * DIM + tid];
  for (int i = tid; i < NNODE; i += 512) s_mask[i] = d_mask[(size_t)b * NNODE + i];
  __syncthreads();

  // ---- glimpse = heads @ w_out + b_out, split-K halves (passing pattern) ----
  {
    int half = tid >> 8;        // 0 or 1
    int col = tid & 255;
    float g = (half == 0) ? b_out[col] : 0.f;
    int d0 = half * 128;
#pragma unroll 8
    for (int d = 0; d < 128; ++d)
      g = fmaf(s_heads[d0 + d], w_out[(size_t)(d0 + d) * DIM + col], g);
    s_gp[half][col] = g;
  }
  __syncthreads();
  if (tid < DIM) s_g[tid] = s_gp[0][tid] + s_gp[1][tid];
  __syncthreads();

  // ---- logits = tanh10(glimpse . L_n / 16), masked; thread owns node tid ----
  {
    const float* Lb = d_L + (size_t)b * DIM * NPAD;
    float a0 = 0.f;
#pragma unroll 8
    for (int d = 0; d < DIM; ++d)
      a0 = fmaf(Lb[(size_t)d * NPAD + tid], s_g[d], a0);
    s_l[tid] = s_mask[tid] ? NEGV : tanh10(a0 * INV_D);
  }
  // node 512: warp 15 lane-strided dot + shuffle tree
  if (w == 15) {
    const float* Lb = d_L + (size_t)b * DIM * NPAD + 512;
    float a = 0.f;
#pragma unroll
    for (int j = 0; j < DIM / 32; ++j)
      a = fmaf(Lb[(size_t)(j * 32 + lane) * NPAD], s_g[j * 32 + lane], a);
#pragma unroll
    for (int o = 16; o; o >>= 1) a += __shfl_xor_sync(0xffffffffu, a, o);
    if (lane == 0) s_l[512] = s_mask[512] ? NEGV : tanh10(a * INV_D);
  }
  __syncthreads();

  // ---- argmax (first occurrence on ties) ----
  float m = -3.402823466e38f;
  int mi = NNODE;
  for (int i = tid; i < NNODE; i += 512) {
    float v = s_l[i];
    if (v > m) { m = v; mi = i; }
  }
#pragma unroll
  for (int o = 16; o; o >>= 1) {
    float om = __shfl_xor_sync(0xffffffffu, m, o);
    int oi = __shfl_xor_sync(0xffffffffu, mi, o);
    if (om > m || (om == m && oi < mi)) { m = om; mi = oi; }
  }
  if (lane == 0) { s_rm[w] = m; s_ri[w] = mi; }
  __syncthreads();
  float mm = s_rm[0];
  int bi = s_ri[0];
#pragma unroll
  for (int i = 1; i < 16; i++) {
    if (s_rm[i] > mm || (s_rm[i] == mm && s_ri[i] < bi)) { mm = s_rm[i]; bi = s_ri[i]; }
  }

  // ---- logsumexp ----
  float s = 0.f;
  for (int i = tid; i < NNODE; i += 512) s += expf(s_l[i] - mm);
#pragma unroll
  for (int o = 16; o; o >>= 1) s += __shfl_xor_sync(0xffffffffu, s, o);
  if (lane == 0) s_rs[w] = s;
  __syncthreads();
  float ss = s_rs[0];
#pragma unroll
  for (int i = 1; i < 16; i++) ss += s_rs[i];
  float lse = mm + logf(ss);

  float* ob = out + ((size_t)b * TSTEPS + t) * NNODE;
  for (int i = tid; i < NNODE; i += 512) ob[i] = s_l[i] - lse;
  if (tid == 0) {
    d_sel[b] = bi;
    if (bi > 0) d_mask[(size_t)b * NNODE + bi] = 1;
  }
}

// ---------------- launch ----------------
extern "C" void kernel_launch(void* const* d_in, const int* in_sizes, int n_in,
                              void* d_out, int out_size) {
  const float* ne     = (const float*)d_in[0];   // (B, N, D)
  const float* ew     = (const float*)d_in[1];   // (B, T, U+1)
  const float* w_kvl  = (const float*)d_in[2];   // (D, 3D)
  const float* b_kvl  = (const float*)d_in[3];
  const float* w_fc   = (const float*)d_in[4];   // (D, D)
  const float* b_fc   = (const float*)d_in[5];
  const float* w_sc   = (const float*)d_in[6];   // (768, D)
  const float* b_sc   = (const float*)d_in[7];
  const float* w_out  = (const float*)d_in[8];   // (D, D)
  const float* b_out  = (const float*)d_in[9];
  const float* w_edge = (const float*)d_in[10];  // (2D, D)
  const float* b_edge = (const float*)d_in[11];
  float* out = (float*)d_out;

  k_precompute_fixed<<<BATCH, 256>>>(ne, w_fc, b_fc);
  k_kvl<<<dim3((BATCH * NNODE) / 64, 768 / 64), 256>>>(ne, w_kvl, b_kvl);

  dim3 gg(BATCH / 32, DIM / 32);   // 16 x 8 = 128 blocks
  for (int t = 0; t < TSTEPS; ++t) {
    k_gemm<<<gg, 256>>>(0, t, ne, ew, w_sc, b_sc, 0.f);
    k_attn<<<dim3(NH, BATCH), 256>>>(t);
    k_fin<<<BATCH, 512>>>(out, w_out, b_out, t);
    k_gemm<<<gg, 256>>>(2, t, ne, ew, w_edge, b_edge, (float)(t + 1));
  }
}

// round 17
// speedup vs baseline: 1.9305x; 1.1316x over previous
#include <cuda_runtime.h>
#include <cuda_pipeline.h>
#include <math.h>

#define BATCH 512
#define NNODE 513
#define NPAD  520          // padded node stride
#define DIM   256
#define NH    8
#define HDIM  32
#define TSTEPS 128
#define EWD   512          // U+1
#define NEGV  -1000000000.0f
#define INV_HD 0.176776695296636893f   // 1/sqrt(32)
#define INV_D  0.0625f                 // 1/sqrt(256)
#define STAGES 4

// ---------------- static device scratch ----------------
// Transposed layouts: K,V = (b, h, d, n_pad)   L = (b, d, n_pad)
static __device__ float d_K[(size_t)BATCH * NH * HDIM * NPAD];
static __device__ float d_V[(size_t)BATCH * NH * HDIM * NPAD];
static __device__ float d_L[(size_t)BATCH * DIM * NPAD];
static __device__ float d_fixed[BATCH * DIM];
static __device__ float d_ctx[BATCH * DIM];      // exact reference recursion space
static __device__ float d_q[BATCH * DIM];
static __device__ float d_heads[BATCH * DIM];
static __device__ int d_sel[BATCH];
static __device__ unsigned char d_mask[BATCH * NNODE];

// 10*tanh(x) via expf so fast-math __tanhf can't perturb the argmax chain.
__device__ __forceinline__ float tanh10(float x) {
  float ax = fabsf(x);
  float t = expf(-2.0f * ax);
  float r = (1.0f - t) / (1.0f + t);
  return copysignf(10.0f * r, x);
}

// ---------------- precompute: graph mean -> fixed_ctx; init state ----------------
__global__ void k_precompute_fixed(const float* __restrict__ ne,
                                   const float* __restrict__ w_fc,
                                   const float* __restrict__ b_fc) {
  int b = blockIdx.x, tid = threadIdx.x;
  __shared__ float mean[DIM];
  const float* base = ne + (size_t)b * NNODE * DIM;
  float acc = 0.f;
  for (int n = 0; n < NNODE; ++n) acc += base[(size_t)n * DIM + tid];
  mean[tid] = acc / (float)NNODE;
  __syncthreads();
  float o = b_fc[tid];
  for (int d = 0; d < DIM; ++d) o += mean[d] * w_fc[d * DIM + tid];
  d_fixed[b * DIM + tid] = o;
  d_ctx[b * DIM + tid] = 0.f;
  for (int i = tid; i < NNODE; i += 256) d_mask[(size_t)b * NNODE + i] = 0;
}

// ---------------- precompute: KVL = node_embeds @ w_kvl + b, scattered transposed ----------------
__global__ void k_kvl(const float* __restrict__ ne,
                      const float* __restrict__ w,
                      const float* __restrict__ bias) {
  __shared__ float As[16][72];
  __shared__ float Bs[16][64];
  int tid = threadIdx.x;
  int tx = tid & 15, ty = tid >> 4;
  int row0 = blockIdx.x * 64;
  int col0 = blockIdx.y * 64;
  int ar = tid >> 2, ac4 = tid & 3;
  int br = tid >> 4, bc4 = tid & 15;
  float acc[4][4];
#pragma unroll
  for (int i = 0; i < 4; i++)
#pragma unroll
    for (int j = 0; j < 4; j++) acc[i][j] = 0.f;

  for (int k0 = 0; k0 < DIM; k0 += 16) {
    float4 av = *(const float4*)&ne[(size_t)(row0 + ar) * DIM + k0 + ac4 * 4];
    As[ac4 * 4 + 0][ar] = av.x;
    As[ac4 * 4 + 1][ar] = av.y;
    As[ac4 * 4 + 2][ar] = av.z;
    As[ac4 * 4 + 3][ar] = av.w;
    *(float4*)&Bs[br][bc4 * 4] =
        *(const float4*)&w[(size_t)(k0 + br) * 768 + col0 + bc4 * 4];
    __syncthreads();
#pragma unroll
    for (int k = 0; k < 16; k++) {
      float4 a = *(const float4*)&As[k][ty * 4];
      float4 bv = *(const float4*)&Bs[k][tx * 4];
      float am[4] = {a.x, a.y, a.z, a.w};
      float bm[4] = {bv.x, bv.y, bv.z, bv.w};
#pragma unroll
      for (int i = 0; i < 4; i++)
#pragma unroll
        for (int j = 0; j < 4; j++) acc[i][j] += am[i] * bm[j];
    }
    __syncthreads();
  }
#pragma unroll
  for (int i = 0; i < 4; i++) {
    int m = row0 + ty * 4 + i;
    int bb = m / NNODE;
    int n = m - bb * NNODE;
#pragma unroll
    for (int j = 0; j < 4; j++) {
      int col = col0 + tx * 4 + j;
      float v = acc[i][j] + bias[col];
      if (col < 256) {
        int h = col >> 5, dd = col & 31;
        d_K[(((size_t)bb * NH + h) * HDIM + dd) * NPAD + n] = v;
      } else if (col < 512) {
        int c = col - 256;
        int h = c >> 5, dd = c & 31;
        d_V[(((size_t)bb * NH + h) * HDIM + dd) * NPAD + n] = v;
      } else {
        d_L[((size_t)bb * DIM + (col - 512)) * NPAD + n] = v;
      }
    }
  }
}

// ---------------- per-step small GEMMs, 32x32 tiles, 4-stage cp.async pipeline ----------------
// mode 0: q = fixed + [ctx | ew_t] @ w_sc + b_sc              (K=768)
// mode 2: ctx += ([sel_emb | curr_emb] @ w_edge + b - ctx)/t  (K=512)
// Per-output: single accumulator, k strictly ascending (unchanged arithmetic).
__global__ __launch_bounds__(256) void k_gemm(int mode, int t,
                                              const float* __restrict__ ne,
                                              const float* __restrict__ ew,
                                              const float* __restrict__ wmat,
                                              const float* __restrict__ bias,
                                              float tf) {
  __shared__ float As[STAGES][32][18];   // [stage][m][k], pad 18 -> 8B-aligned rows
  __shared__ float Bs[STAGES][16][32];   // [stage][k][n]
  int tid = threadIdx.x;
  int tx = tid & 15, ty = tid >> 4;          // outputs: rows ty*2+i, cols tx*2+j
  int row0 = blockIdx.x * 32;
  int col0 = blockIdx.y * 32;
  int ar = tid >> 3, ac2 = (tid & 7) * 2;    // A loader: row 0..31, k-pair
  int br = tid >> 4, bc2 = (tid & 15) * 2;   // B loader: k 0..15, col-pair
  int K = (mode == 0) ? 768 : 512;
  int ntiles = K / 16;
  int m = row0 + ar;
  int sel = (mode == 2) ? d_sel[m] : 0;
  float acc[2][2] = {{0.f, 0.f}, {0.f, 0.f}};

  auto srcA = [&](int k0) -> const float* {
    int kk = k0 + ac2;
    if (mode == 0) {
      if (kk < 256) return &d_ctx[m * DIM + kk];
      return &ew[((size_t)m * TSTEPS + t) * EWD + (kk - 256)];
    } else {
      if (kk < 256) return &ne[((size_t)m * NNODE + sel) * DIM + kk];
      return &ne[((size_t)m * NNODE + (NNODE - 1)) * DIM + (kk - 256)];
    }
  };

  // prologue: prefetch STAGES-1 tiles
#pragma unroll
  for (int st = 0; st < STAGES - 1; ++st) {
    __pipeline_memcpy_async(&As[st][ar][ac2], srcA(st * 16), 8);
    __pipeline_memcpy_async(&Bs[st][br][bc2],
                            &wmat[(size_t)(st * 16 + br) * DIM + col0 + bc2], 8);
    __pipeline_commit();
  }

  for (int ti = 0; ti < ntiles; ++ti) {
    int pf = ti + STAGES - 1;
    if (pf < ntiles) {
      int st = pf % STAGES;   // == (ti-1)%STAGES: stage consumed last iter, safe after its sync
      __pipeline_memcpy_async(&As[st][ar][ac2], srcA(pf * 16), 8);
      __pipeline_memcpy_async(&Bs[st][br][bc2],
                              &wmat[(size_t)(pf * 16 + br) * DIM + col0 + bc2], 8);
    }
    __pipeline_commit();                 // one group per iter keeps counts uniform
    __pipeline_wait_prior(STAGES - 1);   // tile ti's copies (my thread) complete
    __syncthreads();                     // all threads' copies visible
    int p = ti % STAGES;
#pragma unroll
    for (int k = 0; k < 16; k++) {
      float a0 = As[p][ty * 2][k], a1 = As[p][ty * 2 + 1][k];
      float b0 = Bs[p][k][tx * 2], b1 = Bs[p][k][tx * 2 + 1];
      acc[0][0] = fmaf(a0, b0, acc[0][0]);
      acc[0][1] = fmaf(a0, b1, acc[0][1]);
      acc[1][0] = fmaf(a1, b0, acc[1][0]);
      acc[1][1] = fmaf(a1, b1, acc[1][1]);
    }
    __syncthreads();                     // done reading stage p; next iter may refill it
  }

#pragma unroll
  for (int i = 0; i < 2; i++) {
    int mm = row0 + ty * 2 + i;
#pragma unroll
    for (int j = 0; j < 2; j++) {
      int col = col0 + tx * 2 + j;
      float v = acc[i][j] + bias[col];
      if (mode == 0) {
        d_q[mm * DIM + col] = v + d_fixed[mm * DIM + col];
      } else {
        float old = d_ctx[mm * DIM + col];
        d_ctx[mm * DIM + col] = old + (v - old) / tf;
      }
    }
  }
}

// ---------------- per-(b,h) attention kernel: compat -> softmax -> heads ----------------
__global__ __launch_bounds__(256) void k_attn(int t) {
  int h = blockIdx.x, b = blockIdx.y;
  int tid = threadIdx.x, lane = tid & 31, w = tid >> 5;   // 8 warps
  __shared__ float s_q[HDIM];
  __shared__ float s_at[NNODE];
  __shared__ float s_red[8];

  if (tid < HDIM) s_q[tid] = d_q[b * DIM + h * HDIM + tid];
  __syncthreads();

  const unsigned char* mk = d_mask + (size_t)b * NNODE;
  const float* Kh = d_K + ((size_t)(b * NH + h) * HDIM) * NPAD;

  // ---- compat: thread owns nodes tid, tid+256 (tid 0 also 512), d ascending ----
  {
    float a0 = 0.f, a1 = 0.f, a2 = 0.f;
#pragma unroll 8
    for (int d = 0; d < HDIM; ++d) {
      float qv = s_q[d];
      const float* row = Kh + (size_t)d * NPAD;
      a0 = fmaf(row[tid], qv, a0);
      a1 = fmaf(row[tid + 256], qv, a1);
      if (tid == 0) a2 = fmaf(row[512], qv, a2);
    }
    s_at[tid]       = mk[tid]       ? NEGV : a0 * INV_HD;
    s_at[tid + 256] = mk[tid + 256] ? NEGV : a1 * INV_HD;
    if (tid == 0) s_at[512] = mk[512] ? NEGV : a2 * INV_HD;
  }
  __syncthreads();

  // ---- block softmax over 513 ----
  float m = fmaxf(s_at[tid], s_at[tid + 256]);
  if (tid == 0) m = fmaxf(m, s_at[512]);
#pragma unroll
  for (int o = 16; o; o >>= 1) m = fmaxf(m, __shfl_xor_sync(0xffffffffu, m, o));
  if (lane == 0) s_red[w] = m;
  __syncthreads();
  float mm = s_red[0];
#pragma unroll
  for (int i = 1; i < 8; i++) mm = fmaxf(mm, s_red[i]);
  __syncthreads();

  float e0 = expf(s_at[tid] - mm);
  float e1 = expf(s_at[tid + 256] - mm);
  s_at[tid] = e0;
  s_at[tid + 256] = e1;
  float s = e0 + e1;
  if (tid == 0) {
    float e2 = expf(s_at[512] - mm);
    s_at[512] = e2;
    s += e2;
  }
#pragma unroll
  for (int o = 16; o; o >>= 1) s += __shfl_xor_sync(0xffffffffu, s, o);
  __syncthreads();
  if (lane == 0) s_red[w] = s;
  __syncthreads();
  float ss = s_red[0];
#pragma unroll
  for (int i = 1; i < 8; i++) ss += s_red[i];
  float inv = 1.0f / ss;
  s_at[tid] *= inv;
  s_at[tid + 256] *= inv;
  if (tid == 0) s_at[512] *= inv;
  __syncthreads();

  // ---- heads: warp w -> dims w*4..w*4+3, 4 interleaved lane-stride-32 dots ----
  {
    const float* Vh = d_V + ((size_t)(b * NH + h) * HDIM) * NPAD + (size_t)(w * 4) * NPAD;
    float acc[4] = {0.f, 0.f, 0.f, 0.f};
    for (int i = lane; i < NNODE; i += 32) {
      float a = s_at[i];
#pragma unroll
      for (int j = 0; j < 4; ++j) acc[j] = fmaf(a, Vh[(size_t)j * NPAD + i], acc[j]);
    }
#pragma unroll
    for (int j = 0; j < 4; ++j) {
      float v = acc[j];
#pragma unroll
      for (int o = 16; o; o >>= 1) v += __shfl_xor_sync(0xffffffffu, v, o);
      if (lane == 0) d_heads[b * DIM + h * HDIM + w * 4 + j] = v;
    }
  }
}

// ---------------- per-b finish kernel: glimpse -> logits -> argmax -> output ----------------
__global__ __launch_bounds__(512) void k_fin(float* __restrict__ out,
                                             const float* __restrict__ w_out,
                                             const float* __restrict__ b_out,
                                             int t) {
  int b = blockIdx.x;
  int tid = threadIdx.x, lane = tid & 31, w = tid >> 5;   // 16 warps
  __shared__ float s_heads[DIM];
  __shared__ float s_gp[2][DIM];
  __shared__ float s_g[DIM];
  __shared__ float s_l[NNODE];
  __shared__ unsigned char s_mask[NNODE];
  __shared__ float s_rm[16];
  __shared__ int s_ri[16];
  __shared__ float s_rs[16];

  if (tid < DIM) s_heads[tid] = d_heads[b * DIM + tid];
  for (int i = tid; i < NNODE; i += 512) s_mask[i] = d_mask[(size_t)b * NNODE + i];
  __syncthreads();

  // ---- glimpse = heads @ w_out + b_out, split-K halves (passing pattern) ----
  {
    int half = tid >> 8;        // 0 or 1
    int col = tid & 255;
    float g = (half == 0) ? b_out[col] : 0.f;
    int d0 = half * 128;
#pragma unroll 8
    for (int d = 0; d < 128; ++d)
      g = fmaf(s_heads[d0 + d], w_out[(size_t)(d0 + d) * DIM + col], g);
    s_gp[half][col] = g;
  }
  __syncthreads();
  if (tid < DIM) s_g[tid] = s_gp[0][tid] + s_gp[1][tid];
  __syncthreads();

  // ---- logits = tanh10(glimpse . L_n / 16), masked; thread owns node tid ----
  {
    const float* Lb = d_L + (size_t)b * DIM * NPAD;
    float a0 = 0.f;
#pragma unroll 8
    for (int d = 0; d < DIM; ++d)
      a0 = fmaf(Lb[(size_t)d * NPAD + tid], s_g[d], a0);
    s_l[tid] = s_mask[tid] ? NEGV : tanh10(a0 * INV_D);
  }
  // node 512: warp 15 lane-strided dot + shuffle tree
  if (w == 15) {
    const float* Lb = d_L + (size_t)b * DIM * NPAD + 512;
    float a = 0.f;
#pragma unroll
    for (int j = 0; j < DIM / 32; ++j)
      a = fmaf(Lb[(size_t)(j * 32 + lane) * NPAD], s_g[j * 32 + lane], a);
#pragma unroll
    for (int o = 16; o; o >>= 1) a += __shfl_xor_sync(0xffffffffu, a, o);
    if (lane == 0) s_l[512] = s_mask[512] ? NEGV : tanh10(a * INV_D);
  }
  __syncthreads();

  // ---- argmax (first occurrence on ties) ----
  float m = -3.402823466e38f;
  int mi = NNODE;
  for (int i = tid; i < NNODE; i += 512) {
    float v = s_l[i];
    if (v > m) { m = v; mi = i; }
  }
#pragma unroll
  for (int o = 16; o; o >>= 1) {
    float om = __shfl_xor_sync(0xffffffffu, m, o);
    int oi = __shfl_xor_sync(0xffffffffu, mi, o);
    if (om > m || (om == m && oi < mi)) { m = om; mi = oi; }
  }
  if (lane == 0) { s_rm[w] = m; s_ri[w] = mi; }
  __syncthreads();
  float mm = s_rm[0];
  int bi = s_ri[0];
#pragma unroll
  for (int i = 1; i < 16; i++) {
    if (s_rm[i] > mm || (s_rm[i] == mm && s_ri[i] < bi)) { mm = s_rm[i]; bi = s_ri[i]; }
  }

  // ---- logsumexp ----
  float s = 0.f;
  for (int i = tid; i < NNODE; i += 512) s += expf(s_l[i] - mm);
#pragma unroll
  for (int o = 16; o; o >>= 1) s += __shfl_xor_sync(0xffffffffu, s, o);
  if (lane == 0) s_rs[w] = s;
  __syncthreads();
  float ss = s_rs[0];
#pragma unroll
  for (int i = 1; i < 16; i++) ss += s_rs[i];
  float lse = mm + logf(ss);

  float* ob = out + ((size_t)b * TSTEPS + t) * NNODE;
  for (int i = tid; i < NNODE; i += 512) ob[i] = s_l[i] - lse;
  if (tid == 0) {
    d_sel[b] = bi;
    if (bi > 0) d_mask[(size_t)b * NNODE + bi] = 1;
  }
}

// ---------------- launch ----------------
extern "C" void kernel_launch(void* const* d_in, const int* in_sizes, int n_in,
                              void* d_out, int out_size) {
  const float* ne     = (const float*)d_in[0];   // (B, N, D)
  const float* ew     = (const float*)d_in[1];   // (B, T, U+1)
  const float* w_kvl  = (const float*)d_in[2];   // (D, 3D)
  const float* b_kvl  = (const float*)d_in[3];
  const float* w_fc   = (const float*)d_in[4];   // (D, D)
  const float* b_fc   = (const float*)d_in[5];
  const float* w_sc   = (const float*)d_in[6];   // (768, D)
  const float* b_sc   = (const float*)d_in[7];
  const float* w_out  = (const float*)d_in[8];   // (D, D)
  const float* b_out  = (const float*)d_in[9];
  const float* w_edge = (const float*)d_in[10];  // (2D, D)
  const float* b_edge = (const float*)d_in[11];
  float* out = (float*)d_out;

  k_precompute_fixed<<<BATCH, 256>>>(ne, w_fc, b_fc);
  k_kvl<<<dim3((BATCH * NNODE) / 64, 768 / 64), 256>>>(ne, w_kvl, b_kvl);

  dim3 gg(BATCH / 32, DIM / 32);   // 16 x 8 = 128 blocks
  for (int t = 0; t < TSTEPS; ++t) {
    k_gemm<<<gg, 256>>>(0, t, ne, ew, w_sc, b_sc, 0.f);
    k_attn<<<dim3(NH, BATCH), 256>>>(t);
    k_fin<<<BATCH, 512>>>(out, w_out, b_out, t);
    k_gemm<<<gg, 256>>>(2, t, ne, ew, w_edge, b_edge, (float)(t + 1));
  }
}